// round 15
// baseline (speedup 1.0000x reference)
#include <cuda_runtime.h>
#include <cstdint>
#include <math.h>

// Problem constants
#define Bb 16
#define Tt 2048
#define Cc 512
#define Hh 4
#define Kk 31
#define Mm (Bb * Tt)        // 32768 rows

// ---------------- scratch (device globals: allocation-free) ----------------
__device__ float g_w1c[(size_t)2 * Cc * Cc];  // tf32-rounded w1, 2 MB
__device__ float g_w2c[(size_t)Cc * Cc];      // tf32-rounded w2, 1 MB
__device__ float g_glu[(size_t)Mm * Cc];      // GLU output (fp32), 64 MB
__device__ float g_z[(size_t)Mm * Cc];        // post-conv (tf32-rounded), 64 MB

static __device__ __forceinline__ float f2tf32(float f) {
    uint32_t u;
    asm("cvt.rna.tf32.f32 %0, %1;" : "=r"(u) : "f"(f));
    return __uint_as_float(u);
}

static __device__ __forceinline__ uint32_t smem_u32(const void* p) {
    uint32_t a;
    asm("{ .reg .u64 t; cvta.to.shared.u64 t, %1; cvt.u32.u64 %0, t; }"
        : "=r"(a) : "l"(p));
    return a;
}

#define CP16(d, s) \
    asm volatile("cp.async.cg.shared.global [%0], [%1], 16;" \
                 :: "r"(d), "l"(s) : "memory")

#define MMA_TF32(acc, a0, a1, a2, a3, b0, b1) \
    asm volatile( \
        "mma.sync.aligned.m16n8k8.row.col.f32.tf32.tf32.f32 " \
        "{%0,%1,%2,%3}, {%4,%5,%6,%7}, {%8,%9}, {%0,%1,%2,%3};" \
        : "+f"((acc)[0]), "+f"((acc)[1]), "+f"((acc)[2]), "+f"((acc)[3]) \
        : "r"(__float_as_uint(a0)), "r"(__float_as_uint(a1)), \
          "r"(__float_as_uint(a2)), "r"(__float_as_uint(a3)), \
          "r"(__float_as_uint(b0)), "r"(__float_as_uint(b1)))

// Packed f32x2 helpers (sm_100 FFMA2 path)
#define PACK_F32X2(out, lo, hi) \
    asm("mov.b64 %0, {%1, %2};" : "=l"(out) : "f"(lo), "f"(hi))
#define UNPACK_F32X2(lo, hi, in) \
    asm("mov.b64 {%0, %1}, %2;" : "=f"(lo), "=f"(hi) : "l"(in))
#define FMA_F32X2(d, a, b, c) \
    asm("fma.rn.f32x2 %0, %1, %2, %3;" \
        : "=l"(d) : "l"(a), "l"(b), "l"(c))

// ---------------- prepass: rna-round BOTH weights in one launch ----------------
__global__ void __launch_bounds__(256) cvt_w_kernel(
    const float* __restrict__ w1, float* __restrict__ w1c,
    const float* __restrict__ w2, float* __restrict__ w2c,
    int n1_4, int ntot_4)
{
    int i = blockIdx.x * blockDim.x + threadIdx.x;
    if (i >= ntot_4) return;
    const float4* src;
    float4* dst;
    int idx;
    if (i < n1_4) { src = (const float4*)w1; dst = (float4*)w1c; idx = i; }
    else          { src = (const float4*)w2; dst = (float4*)w2c; idx = i - n1_4; }
    float4 v = src[idx];
    v.x = f2tf32(v.x); v.y = f2tf32(v.y);
    v.z = f2tf32(v.z); v.w = f2tf32(v.w);
    dst[idx] = v;
}

// ---------------- tf32 mma.sync GEMM (R8/R11/R13-verified mainloop) ----------------
// C[M,N] = A[M,K] @ B[N,K]^T + bias (+GLU).  A,B row-major K-contiguous.
// B pre-rounded tf32; A pre-rounded (CVTA=false) or rounded in-register
// after the fragment LDS (CVTA=true; numerically identical).
// CTA: 128x128 tile, 128 threads = 4 warps (2x2 of 64x64).  BK=16,
// 4-stage cp.async ring (16KB/stage), main loop unrolled x4 so all stage
// offsets are immediates.
#define GEMM_SMEM 65536

template<bool GLU, bool CVTA>
__global__ void __launch_bounds__(128, 3) gemm_mma(
    const float* __restrict__ A, const float* __restrict__ Bw,
    const float* __restrict__ bias, float* __restrict__ C)
{
    extern __shared__ __align__(16) float smf[];   // 16384 floats
    const int tid  = threadIdx.x;
    const int lane = tid & 31;
    const int wid  = tid >> 5;
    const int wm   = wid & 1;        // warp m: 0..1 (64 rows)
    const int wn   = wid >> 1;       // warp n: 0..1 (64 cols)
    const int bc   = lane & 3;
    const int lq   = lane >> 2;
    const int m0   = blockIdx.y * 128;
    const int colbase = blockIdx.x * (GLU ? 64 : 128);
    const int NK = Cc / 16;          // 32 chunks (multiple of 4)

    // ---- producer: thread t -> smem row prow(+32j), 16B unit punit ----
    const int prow  = tid >> 2;
    const int punit = tid & 3;
    const int swu   = (punit ^ (prow & 3)) << 2;
    const uint32_t smu = smem_u32(smf);
    const uint32_t saA = smu + (uint32_t)prow * 64u + (uint32_t)swu * 4u;
    const uint32_t saB = saA + 8192u;
    const char* gA = (const char*)(A + (size_t)(m0 + prow) * Cc + punit * 4);
    const char* gB = (const char*)(Bw + (size_t)(colbase + prow) * Cc + punit * 4);
    const int BO1 = GLU ? 1048576 : 65536;
    const int BO2 = GLU ? 65536   : 131072;
    const int BO3 = GLU ? 1114112 : 196608;

    float acc[4][8][4];
#pragma unroll
    for (int mt = 0; mt < 4; mt++)
#pragma unroll
        for (int nt = 0; nt < 8; nt++)
#pragma unroll
            for (int i = 0; i < 4; i++) acc[mt][nt][i] = 0.f;

    const int lq3 = lq & 3;
    const int uo0 = ((((bc >> 1)    ) ^ lq3) << 2) + (bc & 1) * 2;
    const int uo1 = ((((bc >> 1) + 2) ^ lq3) << 2) + (bc & 1) * 2;
    const int aoff = wm * 1024 + lq * 16;
    const int boff = 2048 + wn * 1024 + lq * 16;

    auto issue = [&](uint32_t so, const char* ga, const char* gb) {
        CP16(saA + so,         ga);
        CP16(saA + so + 2048u, ga + 65536);
        CP16(saA + so + 4096u, ga + 131072);
        CP16(saA + so + 6144u, ga + 196608);
        CP16(saB + so,         gb);
        CP16(saB + so + 2048u, gb + BO1);
        CP16(saB + so + 4096u, gb + BO2);
        CP16(saB + so + 6144u, gb + BO3);
        asm volatile("cp.async.commit_group;" ::: "memory");
    };

    issue(0u,      gA,       gB);
    issue(16384u,  gA + 64,  gB + 64);
    issue(32768u,  gA + 128, gB + 128);

#pragma unroll 1
    for (int kt4 = 0; kt4 < NK; kt4 += 4) {
        const char* ga4 = gA + (size_t)(kt4 + 3) * 64;
        const char* gb4 = gB + (size_t)(kt4 + 3) * 64;
#pragma unroll
        for (int j = 0; j < 4; j++) {
            const int kt = kt4 + j;
            asm volatile("cp.async.wait_group 2;" ::: "memory");
            __syncthreads();
            if (kt + 3 < NK)
                issue((uint32_t)(((j + 3) & 3) * 16384), ga4 + j * 64, gb4 + j * 64);
            else
                asm volatile("cp.async.commit_group;" ::: "memory");

            const float* sA = smf + j * 4096 + aoff;   // compile-time stage
            const float* sB = smf + j * 4096 + boff;
#pragma unroll
            for (int s = 0; s < 2; s++) {
                const int uo = s ? uo1 : uo0;
                float af[4][4];
#pragma unroll
                for (int mt = 0; mt < 4; mt++) {
                    const float2 v0 = *(const float2*)(sA + uo + mt * 256);
                    const float2 v1 = *(const float2*)(sA + uo + mt * 256 + 128);
                    af[mt][0] = v0.x; af[mt][1] = v1.x;
                    af[mt][2] = v0.y; af[mt][3] = v1.y;
                    if (CVTA) {
                        af[mt][0] = f2tf32(af[mt][0]);
                        af[mt][1] = f2tf32(af[mt][1]);
                        af[mt][2] = f2tf32(af[mt][2]);
                        af[mt][3] = f2tf32(af[mt][3]);
                    }
                }
                float2 bvv[2];
                bvv[0] = *(const float2*)(sB + uo);
#pragma unroll
                for (int nt = 0; nt < 8; nt++) {
                    if (nt < 7)
                        bvv[(nt + 1) & 1] = *(const float2*)(sB + uo + (nt + 1) * 128);
                    const float2 bv = bvv[nt & 1];
#pragma unroll
                    for (int mt = 0; mt < 4; mt++) {
                        MMA_TF32(acc[mt][nt],
                                 af[mt][0], af[mt][1], af[mt][2], af[mt][3],
                                 bv.x, bv.y);
                    }
                }
            }
        }
    }

    // ---- epilogue ----
    if (GLU) {
#pragma unroll
        for (int mt = 0; mt < 4; mt++) {
            const int r = m0 + wm * 64 + mt * 16 + lq;
#pragma unroll
            for (int nt = 0; nt < 4; nt++) {
                const int col = colbase + wn * 32 + nt * 8 + bc * 2;
                const float2 ba = *(const float2*)&bias[col];
                const float2 bg = *(const float2*)&bias[512 + col];
                float2 o;
                {
                    const float a0 = acc[mt][nt][0] + ba.x, a1 = acc[mt][nt][1] + ba.y;
                    const float g0 = acc[mt][nt + 4][0] + bg.x, g1 = acc[mt][nt + 4][1] + bg.y;
                    o.x = a0 / (1.f + __expf(-g0));
                    o.y = a1 / (1.f + __expf(-g1));
                    *(float2*)&C[(size_t)r * Cc + col] = o;
                }
                {
                    const float a0 = acc[mt][nt][2] + ba.x, a1 = acc[mt][nt][3] + ba.y;
                    const float g0 = acc[mt][nt + 4][2] + bg.x, g1 = acc[mt][nt + 4][3] + bg.y;
                    o.x = a0 / (1.f + __expf(-g0));
                    o.y = a1 / (1.f + __expf(-g1));
                    *(float2*)&C[(size_t)(r + 8) * Cc + col] = o;
                }
            }
        }
    } else {
#pragma unroll
        for (int mt = 0; mt < 4; mt++) {
            const int r = m0 + wm * 64 + mt * 16 + lq;
#pragma unroll
            for (int nt = 0; nt < 8; nt++) {
                const int col = colbase + wn * 64 + nt * 8 + bc * 2;
                const float2 bb = *(const float2*)&bias[col];
                float2 o;
                o.x = acc[mt][nt][0] + bb.x;
                o.y = acc[mt][nt][1] + bb.y;
                *(float2*)&C[(size_t)r * Cc + col] = o;
                o.x = acc[mt][nt][2] + bb.x;
                o.y = acc[mt][nt][3] + bb.y;
                *(float2*)&C[(size_t)(r + 8) * Cc + col] = o;
            }
        }
    }
}

// ---------------- depthwise LightConv — packed f32x2 (FFMA2) version ----------
// Each thread: channel PAIR (2cl, 2cl+1) x 16 t-rows.  Adjacent channels =>
// window loads are single LDS.64, stores STG.64.  The two channels use
// kernels h=2(cl&1) and h=2(cl&1)+1, packed per-tap: wr2[k]=(w[h][k],w[h+1][k]).
// Tap accumulation order per output identical to the scalar version =>
// bit-identical z.
#define TT 64
#define TC 64
#define PAD 15
#define SROWS (TT + 2 * PAD)   // 94

__global__ __launch_bounds__(128, 4) void lconv_kernel(
    const float* __restrict__ glu, const float* __restrict__ lw,
    const float* __restrict__ lbias, float* __restrict__ z)
{
    __shared__ float s[SROWS][TC];
    __shared__ float2 wk2[2][Kk];   // pair-class -> packed taps

    const int tid = threadIdx.x;
    const int t0 = blockIdx.x * TT;
    const int c0 = blockIdx.y * TC;
    const int b  = blockIdx.z;

    // softmax: thread p in {0,1} handles kernels h=2p and h=2p+1, packs them
    if (tid < 2) {
        float wa[Kk], wb[Kk];
#pragma unroll
        for (int half = 0; half < 2; half++) {
            const float* row = lw + (2 * tid + half) * Kk;
            float mx = -1e30f;
#pragma unroll
            for (int k = 0; k < Kk; k++) mx = fmaxf(mx, row[k]);
            float sum = 0.f;
            float* dst = half ? wb : wa;
#pragma unroll
            for (int k = 0; k < Kk; k++) { dst[k] = __expf(row[k] - mx); sum += dst[k]; }
            const float inv = 1.f / sum;
#pragma unroll
            for (int k = 0; k < Kk; k++) dst[k] *= inv;
        }
#pragma unroll
        for (int k = 0; k < Kk; k++) wk2[tid][k] = make_float2(wa[k], wb[k]);
    }

    // load tile (halo 15 each side), 128 threads
    const float* yb = glu + (size_t)b * Tt * Cc;
    for (int idx = tid; idx < SROWS * (TC / 4); idx += 128) {
        const int r = idx / (TC / 4);
        const int v = idx % (TC / 4);
        const int t = t0 - PAD + r;
        float4 o;
        if (t >= 0 && t < Tt) {
            o = *(const float4*)&yb[(size_t)t * Cc + c0 + v * 4];
        } else {
            o.x = o.y = o.z = o.w = 0.f;
        }
        *(float4*)&s[r][v * 4] = o;
    }
    __syncthreads();

    const int cl = tid & 31;        // channel-pair id: channels 2cl, 2cl+1
    const int tg = tid >> 5;        // 0..3, rows tg*16 .. tg*16+15
    const int pc = cl & 1;          // pair class: (h0,h1) or (h2,h3)

    // packed taps in registers (31 x b64)
    unsigned long long wr2[Kk];
#pragma unroll
    for (int k = 0; k < Kk; k++) {
        const float2 w = wk2[pc][k];
        PACK_F32X2(wr2[k], w.x, w.y);
    }

    // packed bias init
    const float2 bv2 = *(const float2*)&lbias[c0 + 2 * cl];
    unsigned long long bpack;
    PACK_F32X2(bpack, bv2.x, bv2.y);
    unsigned long long acc2[16];
#pragma unroll
    for (int i = 0; i < 16; i++) acc2[i] = bpack;

    // scatter-accumulate: 46 window loads feed 16 outputs x 31 taps (x2 ch)
#pragma unroll
    for (int w = 0; w < TT / 4 + Kk - 1; w++) {   // 46
        const float2 v = *(const float2*)&s[tg * 16 + w][2 * cl];
        unsigned long long vp;
        PACK_F32X2(vp, v.x, v.y);
        const int ilo = (w - (Kk - 1)) > 0 ? (w - (Kk - 1)) : 0;
        const int ihi = w < 15 ? w : 15;
#pragma unroll
        for (int i = ilo; i <= ihi; i++)
            FMA_F32X2(acc2[i], wr2[w - i], vp, acc2[i]);
    }

    // store: tf32-round both lanes, STG.64
    float* zb = z + ((size_t)b * Tt + t0 + tg * 16) * Cc + c0 + 2 * cl;
#pragma unroll
    for (int i = 0; i < 16; i++) {
        float lo, hi;
        UNPACK_F32X2(lo, hi, acc2[i]);
        float2 o;
        o.x = f2tf32(lo);
        o.y = f2tf32(hi);
        *(float2*)&zb[(size_t)i * Cc] = o;
    }
}

// ---------------- launch ----------------
extern "C" void kernel_launch(void* const* d_in, const int* in_sizes, int n_in,
                              void* d_out, int out_size)
{
    const float* x     = (const float*)d_in[0];
    const float* lw    = (const float*)d_in[1];
    const float* lbias = (const float*)d_in[2];
    const float* w1    = (const float*)d_in[3];
    const float* b1    = (const float*)d_in[4];
    const float* w2    = (const float*)d_in[5];
    const float* b2    = (const float*)d_in[6];
    float* out = (float*)d_out;

    float *w1c, *w2c, *glup, *zp;
    cudaGetSymbolAddress((void**)&w1c,  g_w1c);
    cudaGetSymbolAddress((void**)&w2c,  g_w2c);
    cudaGetSymbolAddress((void**)&glup, g_glu);
    cudaGetSymbolAddress((void**)&zp,   g_z);

    cudaFuncSetAttribute((const void*)gemm_mma<true, true>,
                         cudaFuncAttributeMaxDynamicSharedMemorySize, GEMM_SMEM);
    cudaFuncSetAttribute((const void*)gemm_mma<false, false>,
                         cudaFuncAttributeMaxDynamicSharedMemorySize, GEMM_SMEM);

    // prepass: rna-round both weights in ONE launch
    const int n1_4 = 2 * Cc * Cc / 4;
    const int ntot_4 = n1_4 + Cc * Cc / 4;
    cvt_w_kernel<<<(ntot_4 + 255) / 256, 256>>>(w1, w1c, w2, w2c, n1_4, ntot_4);

    // GEMM1 + bias + GLU (A = raw x, rounded in-register)
    gemm_mma<true, true><<<dim3(Cc / 64, Mm / 128), 128, GEMM_SMEM>>>(x, w1c, b1, glup);

    // depthwise LightConv + bias (+ tf32 rounding of z) — FFMA2 version
    lconv_kernel<<<dim3(Tt / TT, Cc / TC, Bb), 128>>>(glup, lw, lbias, zp);

    // GEMM2 + bias (128x128 champion config)
    gemm_mma<false, false><<<dim3(Cc / 128, Mm / 128), 128, GEMM_SMEM>>>(zp, w2c, b2, out);
}

// round 16
// speedup vs baseline: 1.0592x; 1.0592x over previous
#include <cuda_runtime.h>
#include <cstdint>
#include <math.h>

// Problem constants
#define Bb 16
#define Tt 2048
#define Cc 512
#define Hh 4
#define Kk 31
#define Mm (Bb * Tt)        // 32768 rows

// ---------------- scratch (device globals: allocation-free) ----------------
__device__ float g_w1c[(size_t)2 * Cc * Cc];  // tf32-rounded w1, 2 MB
__device__ float g_w2c[(size_t)Cc * Cc];      // tf32-rounded w2, 1 MB
__device__ float g_glu[(size_t)Mm * Cc];      // GLU output (fp32), 64 MB
__device__ float g_z[(size_t)Mm * Cc];        // post-conv (tf32-rounded), 64 MB

static __device__ __forceinline__ float f2tf32(float f) {
    uint32_t u;
    asm("cvt.rna.tf32.f32 %0, %1;" : "=r"(u) : "f"(f));
    return __uint_as_float(u);
}

static __device__ __forceinline__ uint32_t smem_u32(const void* p) {
    uint32_t a;
    asm("{ .reg .u64 t; cvta.to.shared.u64 t, %1; cvt.u32.u64 %0, t; }"
        : "=r"(a) : "l"(p));
    return a;
}

#define CP16(d, s) \
    asm volatile("cp.async.cg.shared.global [%0], [%1], 16;" \
                 :: "r"(d), "l"(s) : "memory")

#define MMA_TF32(acc, a0, a1, a2, a3, b0, b1) \
    asm volatile( \
        "mma.sync.aligned.m16n8k8.row.col.f32.tf32.tf32.f32 " \
        "{%0,%1,%2,%3}, {%4,%5,%6,%7}, {%8,%9}, {%0,%1,%2,%3};" \
        : "+f"((acc)[0]), "+f"((acc)[1]), "+f"((acc)[2]), "+f"((acc)[3]) \
        : "r"(__float_as_uint(a0)), "r"(__float_as_uint(a1)), \
          "r"(__float_as_uint(a2)), "r"(__float_as_uint(a3)), \
          "r"(__float_as_uint(b0)), "r"(__float_as_uint(b1)))

// ---------------- prepass: rna-round BOTH weights in one launch ----------------
__global__ void __launch_bounds__(256) cvt_w_kernel(
    const float* __restrict__ w1, float* __restrict__ w1c,
    const float* __restrict__ w2, float* __restrict__ w2c,
    int n1_4, int ntot_4)
{
    int i = blockIdx.x * blockDim.x + threadIdx.x;
    if (i >= ntot_4) return;
    const float4* src;
    float4* dst;
    int idx;
    if (i < n1_4) { src = (const float4*)w1; dst = (float4*)w1c; idx = i; }
    else          { src = (const float4*)w2; dst = (float4*)w2c; idx = i - n1_4; }
    float4 v = src[idx];
    v.x = f2tf32(v.x); v.y = f2tf32(v.y);
    v.z = f2tf32(v.z); v.w = f2tf32(v.w);
    dst[idx] = v;
}

// ---------------- tf32 mma.sync GEMM (R8/R11/R13-verified mainloop) ----------------
// C[M,N] = A[M,K] @ B[N,K]^T + bias (+GLU).  A,B row-major K-contiguous.
// B pre-rounded tf32.  A: pre-rounded (CVTA=false, GEMM2 path: z rounded by
// conv store) or — for GEMM1 — raw fp32 fed directly to HMMA.tf32, which
// reads the top 19 bits (truncation semantics, cutlass fast-tf32 path).
// CTA: 128x128 tile, 128 threads = 4 warps (2x2 of 64x64).  BK=16,
// 4-stage cp.async ring (16KB/stage), main loop unrolled x4 so all stage
// offsets are immediates.
//
// Smem stage layout (4096 floats): A rows 0..127 x 16 floats, then B.
// float_idx(row,k) = row*16 + ((k>>2) ^ (row&3))*4 + (k&3)   (XOR swizzle)
// mma k-relabel: slot bc <-> storage 2bc, slot bc+4 <-> storage 2bc+1
// (same bijection for A and B => dot product unchanged).
//
// GLU mode: smem B rows [0,32)=a cols cb+[0,32), [32,64)=g same cols,
// [64,96)=a cols cb+32+[0,32), [96,128)=g; epilogue a*sigmoid(g).
#define GEMM_SMEM 65536

template<bool GLU, bool CVTA>
__global__ void __launch_bounds__(128, 3) gemm_mma(
    const float* __restrict__ A, const float* __restrict__ Bw,
    const float* __restrict__ bias, float* __restrict__ C)
{
    extern __shared__ __align__(16) float smf[];   // 16384 floats
    const int tid  = threadIdx.x;
    const int lane = tid & 31;
    const int wid  = tid >> 5;
    const int wm   = wid & 1;        // warp m: 0..1 (64 rows)
    const int wn   = wid >> 1;       // warp n: 0..1 (64 cols)
    const int bc   = lane & 3;
    const int lq   = lane >> 2;
    const int m0   = blockIdx.y * 128;
    const int colbase = blockIdx.x * (GLU ? 64 : 128);
    const int NK = Cc / 16;          // 32 chunks (multiple of 4)

    // ---- producer: thread t -> smem row prow(+32j), 16B unit punit ----
    const int prow  = tid >> 2;
    const int punit = tid & 3;
    const int swu   = (punit ^ (prow & 3)) << 2;
    const uint32_t smu = smem_u32(smf);
    const uint32_t saA = smu + (uint32_t)prow * 64u + (uint32_t)swu * 4u;
    const uint32_t saB = saA + 8192u;
    const char* gA = (const char*)(A + (size_t)(m0 + prow) * Cc + punit * 4);
    const char* gB = (const char*)(Bw + (size_t)(colbase + prow) * Cc + punit * 4);
    // byte offsets of smem-row groups j=0..3 in the B source
    const int BO1 = GLU ? 1048576 : 65536;    // 512*2048  : 32*2048
    const int BO2 = GLU ? 65536   : 131072;   // 32*2048   : 64*2048
    const int BO3 = GLU ? 1114112 : 196608;   // 544*2048  : 96*2048

    float acc[4][8][4];
#pragma unroll
    for (int mt = 0; mt < 4; mt++)
#pragma unroll
        for (int nt = 0; nt < 8; nt++)
#pragma unroll
            for (int i = 0; i < 4; i++) acc[mt][nt][i] = 0.f;

    // consumer loop-invariant offsets (floats)
    const int lq3 = lq & 3;
    const int uo0 = ((((bc >> 1)    ) ^ lq3) << 2) + (bc & 1) * 2;
    const int uo1 = ((((bc >> 1) + 2) ^ lq3) << 2) + (bc & 1) * 2;
    const int aoff = wm * 1024 + lq * 16;
    const int boff = 2048 + wn * 1024 + lq * 16;

    auto issue = [&](uint32_t so, const char* ga, const char* gb) {
        CP16(saA + so,         ga);
        CP16(saA + so + 2048u, ga + 65536);
        CP16(saA + so + 4096u, ga + 131072);
        CP16(saA + so + 6144u, ga + 196608);
        CP16(saB + so,         gb);
        CP16(saB + so + 2048u, gb + BO1);
        CP16(saB + so + 4096u, gb + BO2);
        CP16(saB + so + 6144u, gb + BO3);
        asm volatile("cp.async.commit_group;" ::: "memory");
    };

    issue(0u,      gA,       gB);
    issue(16384u,  gA + 64,  gB + 64);
    issue(32768u,  gA + 128, gB + 128);

#pragma unroll 1
    for (int kt4 = 0; kt4 < NK; kt4 += 4) {
        const char* ga4 = gA + (size_t)(kt4 + 3) * 64;
        const char* gb4 = gB + (size_t)(kt4 + 3) * 64;
#pragma unroll
        for (int j = 0; j < 4; j++) {
            const int kt = kt4 + j;
            asm volatile("cp.async.wait_group 2;" ::: "memory");
            __syncthreads();
            if (kt + 3 < NK)
                issue((uint32_t)(((j + 3) & 3) * 16384), ga4 + j * 64, gb4 + j * 64);
            else
                asm volatile("cp.async.commit_group;" ::: "memory");

            const float* sA = smf + j * 4096 + aoff;   // compile-time stage
            const float* sB = smf + j * 4096 + boff;
#pragma unroll
            for (int s = 0; s < 2; s++) {
                const int uo = s ? uo1 : uo0;
                float af[4][4];
#pragma unroll
                for (int mt = 0; mt < 4; mt++) {
                    const float2 v0 = *(const float2*)(sA + uo + mt * 256);
                    const float2 v1 = *(const float2*)(sA + uo + mt * 256 + 128);
                    af[mt][0] = v0.x; af[mt][1] = v1.x;
                    af[mt][2] = v0.y; af[mt][3] = v1.y;
                    if (CVTA) {
                        af[mt][0] = f2tf32(af[mt][0]);
                        af[mt][1] = f2tf32(af[mt][1]);
                        af[mt][2] = f2tf32(af[mt][2]);
                        af[mt][3] = f2tf32(af[mt][3]);
                    }
                }
                // B double-buffer: prefetch nt+1 while MMAing nt
                float2 bvv[2];
                bvv[0] = *(const float2*)(sB + uo);
#pragma unroll
                for (int nt = 0; nt < 8; nt++) {
                    if (nt < 7)
                        bvv[(nt + 1) & 1] = *(const float2*)(sB + uo + (nt + 1) * 128);
                    const float2 bv = bvv[nt & 1];
#pragma unroll
                    for (int mt = 0; mt < 4; mt++) {
                        MMA_TF32(acc[mt][nt],
                                 af[mt][0], af[mt][1], af[mt][2], af[mt][3],
                                 bv.x, bv.y);
                    }
                }
            }
        }
    }

    // ---- epilogue ----
    if (GLU) {
#pragma unroll
        for (int mt = 0; mt < 4; mt++) {
            const int r = m0 + wm * 64 + mt * 16 + lq;
#pragma unroll
            for (int nt = 0; nt < 4; nt++) {
                const int col = colbase + wn * 32 + nt * 8 + bc * 2;
                const float2 ba = *(const float2*)&bias[col];
                const float2 bg = *(const float2*)&bias[512 + col];
                float2 o;
                {
                    const float a0 = acc[mt][nt][0] + ba.x, a1 = acc[mt][nt][1] + ba.y;
                    const float g0 = acc[mt][nt + 4][0] + bg.x, g1 = acc[mt][nt + 4][1] + bg.y;
                    o.x = a0 / (1.f + __expf(-g0));
                    o.y = a1 / (1.f + __expf(-g1));
                    *(float2*)&C[(size_t)r * Cc + col] = o;
                }
                {
                    const float a0 = acc[mt][nt][2] + ba.x, a1 = acc[mt][nt][3] + ba.y;
                    const float g0 = acc[mt][nt + 4][2] + bg.x, g1 = acc[mt][nt + 4][3] + bg.y;
                    o.x = a0 / (1.f + __expf(-g0));
                    o.y = a1 / (1.f + __expf(-g1));
                    *(float2*)&C[(size_t)(r + 8) * Cc + col] = o;
                }
            }
        }
    } else {
#pragma unroll
        for (int mt = 0; mt < 4; mt++) {
            const int r = m0 + wm * 64 + mt * 16 + lq;
#pragma unroll
            for (int nt = 0; nt < 8; nt++) {
                const int col = colbase + wn * 64 + nt * 8 + bc * 2;
                const float2 bb = *(const float2*)&bias[col];
                float2 o;
                o.x = acc[mt][nt][0] + bb.x;
                o.y = acc[mt][nt][1] + bb.y;
                *(float2*)&C[(size_t)r * Cc + col] = o;
                o.x = acc[mt][nt][2] + bb.x;
                o.y = acc[mt][nt][3] + bb.y;
                *(float2*)&C[(size_t)(r + 8) * Cc + col] = o;
            }
        }
    }
}

// ---------------- depthwise LightConv (R14-verified scalar version) ----------------
#define TT 64
#define TC 64
#define PAD 15
#define SROWS (TT + 2 * PAD)   // 94

__global__ __launch_bounds__(256, 5) void lconv_kernel(
    const float* __restrict__ glu, const float* __restrict__ lw,
    const float* __restrict__ lbias, float* __restrict__ z)
{
    __shared__ float s[SROWS][TC];
    __shared__ float wk[Hh][Kk];

    const int tid = threadIdx.x;
    const int t0 = blockIdx.x * TT;
    const int c0 = blockIdx.y * TC;
    const int b  = blockIdx.z;

    if (tid < Hh) {
        float mx = -1e30f;
#pragma unroll
        for (int k = 0; k < Kk; k++) mx = fmaxf(mx, lw[tid * Kk + k]);
        float sum = 0.f;
        float e[Kk];
#pragma unroll
        for (int k = 0; k < Kk; k++) { e[k] = __expf(lw[tid * Kk + k] - mx); sum += e[k]; }
        const float inv = 1.f / sum;
#pragma unroll
        for (int k = 0; k < Kk; k++) wk[tid][k] = e[k] * inv;
    }

    const float* yb = glu + (size_t)b * Tt * Cc;
    for (int idx = tid; idx < SROWS * (TC / 4); idx += 256) {
        const int r = idx / (TC / 4);
        const int v = idx % (TC / 4);
        const int t = t0 - PAD + r;
        float4 o;
        if (t >= 0 && t < Tt) {
            o = *(const float4*)&yb[(size_t)t * Cc + c0 + v * 4];
        } else {
            o.x = o.y = o.z = o.w = 0.f;
        }
        *(float4*)&s[r][v * 4] = o;
    }
    __syncthreads();

    const int cl = tid & (TC - 1);
    const int tg = tid >> 6;
    const int h  = cl & (Hh - 1);

    float wr[Kk];
#pragma unroll
    for (int k = 0; k < Kk; k++) wr[k] = wk[h][k];
    const float bv = lbias[c0 + cl];

    float acc[16];
#pragma unroll
    for (int i = 0; i < 16; i++) acc[i] = bv;
#pragma unroll
    for (int jj = 0; jj < TT / 4 + Kk - 1; jj++) {
        const float v = s[tg * 16 + jj][cl];
        const int ilo = (jj - (Kk - 1)) > 0 ? (jj - (Kk - 1)) : 0;
        const int ihi = jj < 15 ? jj : 15;
#pragma unroll
        for (int i = ilo; i <= ihi; i++)
            acc[i] += wr[jj - i] * v;
    }

    float* zb = z + ((size_t)b * Tt + t0 + tg * 16) * Cc + c0 + cl;
#pragma unroll
    for (int i = 0; i < 16; i++)
        zb[(size_t)i * Cc] = f2tf32(acc[i]);
}

// ---------------- launch ----------------
extern "C" void kernel_launch(void* const* d_in, const int* in_sizes, int n_in,
                              void* d_out, int out_size)
{
    const float* x     = (const float*)d_in[0];
    const float* lw    = (const float*)d_in[1];
    const float* lbias = (const float*)d_in[2];
    const float* w1    = (const float*)d_in[3];
    const float* b1    = (const float*)d_in[4];
    const float* w2    = (const float*)d_in[5];
    const float* b2    = (const float*)d_in[6];
    float* out = (float*)d_out;

    float *w1c, *w2c, *glup, *zp;
    cudaGetSymbolAddress((void**)&w1c,  g_w1c);
    cudaGetSymbolAddress((void**)&w2c,  g_w2c);
    cudaGetSymbolAddress((void**)&glup, g_glu);
    cudaGetSymbolAddress((void**)&zp,   g_z);

    cudaFuncSetAttribute((const void*)gemm_mma<true, false>,
                         cudaFuncAttributeMaxDynamicSharedMemorySize, GEMM_SMEM);
    cudaFuncSetAttribute((const void*)gemm_mma<false, false>,
                         cudaFuncAttributeMaxDynamicSharedMemorySize, GEMM_SMEM);

    // prepass: rna-round both weights in ONE launch
    const int n1_4 = 2 * Cc * Cc / 4;
    const int ntot_4 = n1_4 + Cc * Cc / 4;
    cvt_w_kernel<<<(ntot_4 + 255) / 256, 256>>>(w1, w1c, w2, w2c, n1_4, ntot_4);

    // GEMM1 + bias + GLU (A = raw x; HMMA.tf32 truncation semantics, no cvt)
    gemm_mma<true, false><<<dim3(Cc / 64, Mm / 128), 128, GEMM_SMEM>>>(x, w1c, b1, glup);

    // depthwise LightConv + bias (+ tf32 rounding of z)
    lconv_kernel<<<dim3(Tt / TT, Cc / TC, Bb), 256>>>(glup, lw, lbias, zp);

    // GEMM2 + bias (128x128 champion config; A = z, pre-rounded by conv)
    gemm_mma<false, false><<<dim3(Cc / 128, Mm / 128), 128, GEMM_SMEM>>>(zp, w2c, b2, out);
}